// round 14
// baseline (speedup 1.0000x reference)
#include <cuda_runtime.h>

// LSEP loss: log1p( sum_i [ exp(-x[i,y_i]) * sum_j exp(x[i,j]) ] - B )
//
// Half-group double-buffered pipeline: 3-row groups (255 float4 = 8 chunks of
// 32 lanes) split into two 4-chunk halves. While computing half A of group i,
// half B's 4 LDG.128 are in flight; while computing half B, half A of group
// i+1 (plus its pos gathers) is in flight -> every warp keeps >=4 loads
// outstanding continuously, AND we stay at 4 CTAs/SM (the measured-best
// occupancy point; R13 showed full-group DB at 2 CTAs/SM merely breaks even).
// 2x4 float4 buffers = 32 data regs; total ~58 regs fits launch_bounds(256,4).
// pos gathered one group ahead via targets loaded two ahead; fp32 hot-loop
// accumulator; fp64 deterministic tree reduction; fused last-block-done
// finish (self-resetting counter -> graph-replay safe).

#define NCLS   340
#define RPG    3               // rows per group
#define C4G    255             // float4s per group (3*85)
#define GRID   592             // 148 SMs * 4 CTAs
#define BLOCK  256
#define WPB    (BLOCK / 32)

__device__ double       g_partials[GRID];
__device__ unsigned int g_count = 0;     // wraps via atomicInc -> replay-safe

__device__ __forceinline__ float exp4(float4 v) {
    return __expf(v.x) + __expf(v.y) + __expf(v.z) + __expf(v.w);
}

__global__ __launch_bounds__(BLOCK, 4)   // 64-reg budget, 4 CTAs/SM
void lsep_hdb_kernel(const float* __restrict__ x,
                     const int*   __restrict__ tgt,
                     float*       __restrict__ out,
                     int B)
{
    const int lane   = threadIdx.x & 31;
    const int warp   = threadIdx.x >> 5;
    const int wglob  = blockIdx.x * WPB + warp;
    const int wtotal = GRID * WPB;

    const int nfull = B / RPG;                 // full 3-row groups
    const int rem   = B - nfull * RPG;         // leftover rows (1 for B=65536)

    const bool k7ok = (lane + 224) < C4G;      // lane 31 skips chunk 7

    float acc = 0.0f;

    int p = wglob;
    if (p < nfull) {
        // ---- prologue ----
        const int* tp = tgt + p * RPG;
        int a0 = tp[0], a1 = tp[1], a2 = tp[2];
        const float* xb = x + (size_t)p * RPG * NCLS;
        float pc0 = __ldg(xb + a0);
        float pc1 = __ldg(xb + NCLS + a1);
        float pc2 = __ldg(xb + 2 * NCLS + a2);

        int b0 = 0, b1 = 0, b2 = 0;            // targets for group p+wtotal
        if (p + wtotal < nfull) {
            const int* tn = tgt + (p + wtotal) * RPG;
            b0 = tn[0]; b1 = tn[1]; b2 = tn[2];
        }

        const float4* cur4 = (const float4*)xb;
        float4 h0 = cur4[lane],      h1 = cur4[lane + 32];
        float4 h2 = cur4[lane + 64], h3 = cur4[lane + 96];

        for (;;) {
            const int pn  = p + wtotal;
            const int pnn = p + 2 * wtotal;
            const bool more = pn < nfull;

            // ---- stage A: issue half-B loads, compute half-A ----
            float4 m0 = cur4[lane + 128], m1 = cur4[lane + 160];
            float4 m2 = cur4[lane + 192], m3;
            if (k7ok) m3 = cur4[lane + 224];

            const float e0 = __expf(-pc0);
            const float e1 = __expf(-pc1);
            const float e2 = __expf(-pc2);

            #define EK(k) ((lane + 32*(k)) < 85 ? e0 : \
                           (lane + 32*(k)) < 170 ? e1 : e2)
            acc += EK(0) * exp4(h0);
            acc += EK(1) * exp4(h1);
            acc += EK(2) * exp4(h2);
            acc += EK(3) * exp4(h3);

            // ---- stage B: issue next group's half-A + pos, compute half-B ----
            const float4* nx4 = cur4;
            float4 q0, q1, q2, q3;
            float  pn0 = 0.f, pn1 = 0.f, pn2 = 0.f;
            if (more) {
                const float* xn = x + (size_t)pn * RPG * NCLS;
                nx4 = (const float4*)xn;
                q0 = nx4[lane];      q1 = nx4[lane + 32];
                q2 = nx4[lane + 64]; q3 = nx4[lane + 96];
                pn0 = __ldg(xn + b0);            // b* resident since last iter
                pn1 = __ldg(xn + NCLS + b1);
                pn2 = __ldg(xn + 2 * NCLS + b2);
            }
            int t0 = 0, t1 = 0, t2 = 0;
            if (pnn < nfull) {
                const int* tn = tgt + pnn * RPG;
                t0 = tn[0]; t1 = tn[1]; t2 = tn[2];
            }

            acc += EK(4) * exp4(m0);
            acc += EK(5) * exp4(m1);
            acc += EK(6) * exp4(m2);
            if (k7ok) acc += EK(7) * exp4(m3);
            #undef EK

            if (!more) break;
            h0 = q0; h1 = q1; h2 = q2; h3 = q3;
            pc0 = pn0; pc1 = pn1; pc2 = pn2;
            b0 = t0; b1 = t1; b2 = t2;
            cur4 = nx4;
            p = pn;
        }
    }

    // ---- remainder rows (B % 3): one warp, simple path ----
    if (wglob == 0) {
        for (int r = 0; r < rem; r++) {
            const int row = nfull * RPG + r;
            const float* xr = x + (size_t)row * NCLS;
            const float4* r4 = (const float4*)xr;
            float s = exp4(r4[lane]) + exp4(r4[lane + 32]);
            if (lane < 21) s += exp4(r4[lane + 64]);
            float pos = __ldg(xr + tgt[row]);
            acc += s * __expf(-pos);
        }
    }

    double dacc = (double)acc;                 // one convert per lane

    // ---- block reduction (deterministic) ----
    #pragma unroll
    for (int o = 16; o; o >>= 1)
        dacc += __shfl_xor_sync(0xffffffffu, dacc, o);

    __shared__ double sacc[WPB];
    __shared__ bool   is_last;
    if (lane == 0) sacc[warp] = dacc;
    __syncthreads();

    if (threadIdx.x == 0) {
        double t = 0.0;
        #pragma unroll
        for (int i = 0; i < WPB; i++) t += sacc[i];
        g_partials[blockIdx.x] = t;
        __threadfence();
        unsigned int old = atomicInc(&g_count, GRID - 1);  // wraps to 0
        is_last = (old == GRID - 1);
    }
    __syncthreads();

    // ---- last block: deterministic final reduce + log1p ----
    if (is_last) {
        __threadfence();
        __shared__ double sfin[BLOCK];
        double t = 0.0;
        for (int i = threadIdx.x; i < GRID; i += BLOCK)
            t += g_partials[i];
        sfin[threadIdx.x] = t;
        __syncthreads();
        #pragma unroll
        for (int o = BLOCK / 2; o; o >>= 1) {
            if (threadIdx.x < o) sfin[threadIdx.x] += sfin[threadIdx.x + o];
            __syncthreads();
        }
        if (threadIdx.x == 0)
            out[0] = (float)log1p(sfin[0] - (double)B);
    }
}

extern "C" void kernel_launch(void* const* d_in, const int* in_sizes, int n_in,
                              void* d_out, int out_size)
{
    const float* x   = (const float*)d_in[0];
    const int*   tgt = (const int*)d_in[1];
    float*       out = (float*)d_out;

    int B = in_sizes[0] / NCLS;   // 65536

    lsep_hdb_kernel<<<GRID, BLOCK>>>(x, tgt, out, B);
}